// round 6
// baseline (speedup 1.0000x reference)
#include <cuda_runtime.h>
#include <cuda_bf16.h>
#include <cstdint>

#define HH 128
#define NMAX 50000
#define EMAX 800000
#define BN_EPS 1e-5f
#define APITCH 136
#define WIMG_ELEMS (128 * APITCH)

// ---------------- scratch (no allocations allowed) ----------------
__device__ float g_z[NMAX * HH];
__device__ float g_hA[NMAX * HH];
__device__ float g_hB[NMAX * HH];
__device__ float g_stats[2 * HH];
__device__ int   g_deg[NMAX];
__device__ int   g_cursor[NMAX];
__device__ int   g_rowstart[NMAX + 1];
__device__ int   g_csr[EMAX];
__device__ uint2 g_ahi[NMAX * 32];            // agg hi plane, row-major bf16
__device__ uint2 g_alo[NMAX * 32];            // agg lo plane
__device__ unsigned short g_w[12][WIMG_ELEMS]; // 6 GEMMs x (hi,lo) padded [n][k]

// ---------------- CSR build ----------------
__global__ void count_kernel(const int* __restrict__ dst, int* __restrict__ deg, int E) {
    int e = blockIdx.x * blockDim.x + threadIdx.x;
    if (e < E) atomicAdd(&deg[dst[e]], 1);
}

__global__ void scan_kernel(const int* __restrict__ deg, int* __restrict__ rowstart, int n) {
    __shared__ int warpsum[32];
    __shared__ int s_total;
    __shared__ int s_carry;
    int tid = threadIdx.x, lane = tid & 31, wid = tid >> 5;
    if (tid == 0) s_carry = 0;
    __syncthreads();
    for (int base = 0; base < n; base += 1024) {
        int i = base + tid;
        int v = (i < n) ? deg[i] : 0;
        int incl = v;
#pragma unroll
        for (int off = 1; off < 32; off <<= 1) {
            int t = __shfl_up_sync(0xffffffff, incl, off);
            if (lane >= off) incl += t;
        }
        if (lane == 31) warpsum[wid] = incl;
        __syncthreads();
        if (wid == 0) {
            int w = warpsum[lane];
            int wincl = w;
#pragma unroll
            for (int off = 1; off < 32; off <<= 1) {
                int t = __shfl_up_sync(0xffffffff, wincl, off);
                if (lane >= off) wincl += t;
            }
            warpsum[lane] = wincl - w;
            if (lane == 31) s_total = wincl;
        }
        __syncthreads();
        int carry = s_carry;
        if (i < n) rowstart[i] = carry + warpsum[wid] + incl - v;
        __syncthreads();
        if (tid == 0) s_carry = carry + s_total;
    }
    __syncthreads();
    if (tid == 0) rowstart[n] = s_carry;
}

__global__ void fill_kernel(const int* __restrict__ src, const int* __restrict__ dst,
                            const int* __restrict__ rowstart, int* __restrict__ cursor,
                            int* __restrict__ csr, int E) {
    int e = blockIdx.x * blockDim.x + threadIdx.x;
    if (e >= E) return;
    int d = dst[e];
    int base = __ldg(&rowstart[d]);
    int p = atomicAdd(&cursor[d], 1);
    csr[base + p] = src[e];
}

// ---------------- W pre-conversion: padded transposed hi/lo images -----------
__global__ void wconv_kernel(const float* __restrict__ W,
                             unsigned short* __restrict__ whi,
                             unsigned short* __restrict__ wlo) {
    int i = blockIdx.x * blockDim.x + threadIdx.x;
    if (i >= 128 * 128) return;
    int k = i >> 7, n = i & 127;
    float v = W[i];
    __nv_bfloat16 h = __float2bfloat16_rn(v);
    __nv_bfloat16 l = __float2bfloat16_rn(v - __bfloat162float(h));
    whi[n * APITCH + k] = __bfloat16_as_ushort(h);
    wlo[n * APITCH + k] = __bfloat16_as_ushort(l);
}

// ---------------- aggregate -> bf16 hi/lo planes -----------------------------
__global__ void aggregate_kernel(const float4* __restrict__ h,
                                 const int* __restrict__ rowstart,
                                 const int* __restrict__ csr,
                                 uint2* __restrict__ ahi,
                                 uint2* __restrict__ alo, int N) {
    int warp = (blockIdx.x * blockDim.x + threadIdx.x) >> 5;
    int lane = threadIdx.x & 31;
    if (warp >= N) return;
    int s0 = rowstart[warp], s1 = rowstart[warp + 1];
    float4 acc = __ldg(&h[(size_t)warp * 32 + lane]);
    int j = s0;
    for (; j + 2 <= s1; j += 2) {
        int sa = __ldg(&csr[j]);
        int sb = __ldg(&csr[j + 1]);
        float4 va = __ldg(&h[(size_t)sa * 32 + lane]);
        float4 vb = __ldg(&h[(size_t)sb * 32 + lane]);
        acc.x += va.x + vb.x; acc.y += va.y + vb.y;
        acc.z += va.z + vb.z; acc.w += va.w + vb.w;
    }
    if (j < s1) {
        int sa = __ldg(&csr[j]);
        float4 va = __ldg(&h[(size_t)sa * 32 + lane]);
        acc.x += va.x; acc.y += va.y; acc.z += va.z; acc.w += va.w;
    }
    // split to bf16 hi/lo, pack pairs
    float v[4] = {acc.x, acc.y, acc.z, acc.w};
    uint32_t hi[2], lo[2];
#pragma unroll
    for (int p = 0; p < 2; p++) {
        __nv_bfloat16 h0 = __float2bfloat16_rn(v[2 * p]);
        __nv_bfloat16 h1 = __float2bfloat16_rn(v[2 * p + 1]);
        __nv_bfloat16 l0 = __float2bfloat16_rn(v[2 * p] - __bfloat162float(h0));
        __nv_bfloat16 l1 = __float2bfloat16_rn(v[2 * p + 1] - __bfloat162float(h1));
        hi[p] = (uint32_t)__bfloat16_as_ushort(h0) | ((uint32_t)__bfloat16_as_ushort(h1) << 16);
        lo[p] = (uint32_t)__bfloat16_as_ushort(l0) | ((uint32_t)__bfloat16_as_ushort(l1) << 16);
    }
    ahi[(size_t)warp * 32 + lane] = make_uint2(hi[0], hi[1]);
    alo[(size_t)warp * 32 + lane] = make_uint2(lo[0], lo[1]);
}

// ---------------- HMMA GEMM (mma.sync bf16, hi/lo split) ----------------
#define PLANE_BYTES (128 * APITCH * 2)   // 34816
#define SM_SCALE 0
#define SM_SHIFT 512
#define SM_BIAS  1024
#define SM_AHI   1536
#define SM_ALO   (SM_AHI + PLANE_BYTES)
#define SM_BHI   (SM_ALO + PLANE_BYTES)
#define SM_BLO   (SM_BHI + PLANE_BYTES)
#define SM_TOTAL (SM_BLO + PLANE_BYTES)  // 140800

__device__ __forceinline__ void mma16816(float* d, const uint32_t* a, const uint32_t* b) {
    asm volatile(
        "mma.sync.aligned.m16n8k16.row.col.f32.bf16.bf16.f32 "
        "{%0,%1,%2,%3}, {%4,%5,%6,%7}, {%8,%9}, {%0,%1,%2,%3};"
        : "+f"(d[0]), "+f"(d[1]), "+f"(d[2]), "+f"(d[3])
        : "r"(a[0]), "r"(a[1]), "r"(a[2]), "r"(a[3]), "r"(b[0]), "r"(b[1]));
}

__device__ __forceinline__ void split_bf16x2(float a0, float a1,
                                             uint32_t& hi, uint32_t& lo) {
    __nv_bfloat16 h0 = __float2bfloat16_rn(a0);
    __nv_bfloat16 h1 = __float2bfloat16_rn(a1);
    __nv_bfloat16 l0 = __float2bfloat16_rn(a0 - __bfloat162float(h0));
    __nv_bfloat16 l1 = __float2bfloat16_rn(a1 - __bfloat162float(h1));
    hi = (uint32_t)__bfloat16_as_ushort(h0) | ((uint32_t)__bfloat16_as_ushort(h1) << 16);
    lo = (uint32_t)__bfloat16_as_ushort(l0) | ((uint32_t)__bfloat16_as_ushort(l1) << 16);
}

// MODE 0: A from preconverted planes (ahi/alo); out=z; fused BN stats
// MODE 1: A = relu(z*scale+shift) from fp32 z; out = relu(.)
template <int MODE>
__global__ __launch_bounds__(256, 1) void gemm_mma(
    const float* __restrict__ Af32,
    const uint4* __restrict__ Ahi, const uint4* __restrict__ Alo,
    const uint4* __restrict__ Whi, const uint4* __restrict__ Wlo,
    const float* __restrict__ bias, const float* __restrict__ gamma,
    const float* __restrict__ beta, float inv_n,
    float* __restrict__ out, int nrows) {
    extern __shared__ char smem[];
    int tid = threadIdx.x;
    int lane = tid & 31;
    int wid = tid >> 5;
    int groupID = lane >> 2;
    int tig = lane & 3;
    int warp_m = wid & 1;
    int warp_n = wid >> 1;
    int block_row = blockIdx.x * 128;

    float* sh_scale = (float*)(smem + SM_SCALE);
    float* sh_shift = (float*)(smem + SM_SHIFT);
    float* sh_bias  = (float*)(smem + SM_BIAS);

    if (tid < 128) {
        sh_bias[tid] = bias[tid];
        if (MODE == 1) {
            float mu = g_stats[tid] * inv_n;
            float var = fmaf(-mu, mu, g_stats[128 + tid] * inv_n);
            float rs = rsqrtf(var + BN_EPS);
            float sc = gamma[tid] * rs;
            sh_scale[tid] = sc;
            sh_shift[tid] = fmaf(-mu, sc, beta[tid]);
        }
    }
    // ---- W tiles: straight copy of precomputed padded images ----
    {
        uint4* dh = (uint4*)(smem + SM_BHI);
        uint4* dl = (uint4*)(smem + SM_BLO);
        for (int i = tid; i < PLANE_BYTES / 16; i += 256) {
            dh[i] = __ldg(&Whi[i]);
            dl[i] = __ldg(&Wlo[i]);
        }
    }
    if (MODE == 1) __syncthreads();   // sh_scale/shift ready before A transform

    // ---- A tile ----
    if (MODE == 0) {
        int r = tid >> 1, half = tid & 1;
        int grow = block_row + r;
        uint32_t dbase = (uint32_t)r * (APITCH * 2) + half * 128;
        const uint4* srch = Ahi + (size_t)grow * 16 + half * 8;
        const uint4* srcl = Alo + (size_t)grow * 16 + half * 8;
#pragma unroll
        for (int i = 0; i < 8; i++) {
            uint4 vh, vl;
            if (grow < nrows) {
                vh = __ldg(&srch[i]);
                vl = __ldg(&srcl[i]);
            } else {
                vh = make_uint4(0, 0, 0, 0);
                vl = make_uint4(0, 0, 0, 0);
            }
            *reinterpret_cast<uint4*>(smem + SM_AHI + dbase + i * 16) = vh;
            *reinterpret_cast<uint4*>(smem + SM_ALO + dbase + i * 16) = vl;
        }
    } else {
        int r = tid >> 1, half = tid & 1;
        int grow = block_row + r;
        const float4* arow =
            reinterpret_cast<const float4*>(Af32 + (size_t)grow * HH + half * 64);
        uint32_t dbase = (uint32_t)r * (APITCH * 2) + half * 128;
#pragma unroll
        for (int i = 0; i < 8; i++) {
            float v[8];
            if (grow < nrows) {
                float4 p0 = arow[2 * i], p1 = arow[2 * i + 1];
                v[0] = p0.x; v[1] = p0.y; v[2] = p0.z; v[3] = p0.w;
                v[4] = p1.x; v[5] = p1.y; v[6] = p1.z; v[7] = p1.w;
                int c0 = half * 64 + i * 8;
#pragma unroll
                for (int j = 0; j < 8; j++)
                    v[j] = fmaxf(fmaf(v[j], sh_scale[c0 + j], sh_shift[c0 + j]), 0.f);
            } else {
#pragma unroll
                for (int j = 0; j < 8; j++) v[j] = 0.f;
            }
            uint32_t hi[4], lo[4];
#pragma unroll
            for (int j = 0; j < 4; j++)
                split_bf16x2(v[2 * j], v[2 * j + 1], hi[j], lo[j]);
            uint32_t off = dbase + i * 16;
            *reinterpret_cast<uint4*>(smem + SM_AHI + off) =
                make_uint4(hi[0], hi[1], hi[2], hi[3]);
            *reinterpret_cast<uint4*>(smem + SM_ALO + off) =
                make_uint4(lo[0], lo[1], lo[2], lo[3]);
        }
    }
    __syncthreads();

    // ---- mainloop: 8 k-steps of 16; 3 terms (hh, hl, lh) ----
    float acc[4][4][4] = {};
#pragma unroll
    for (int ks = 0; ks < 8; ks++) {
        uint32_t kb = (uint32_t)ks * 32 + tig * 4;
        uint32_t ah[4][4], al[4][4], bh[4][2], bl[4][2];
#pragma unroll
        for (int mf = 0; mf < 4; mf++) {
            uint32_t base = (uint32_t)(warp_m * 64 + mf * 16 + groupID) * (APITCH * 2) + kb;
            ah[mf][0] = *(const uint32_t*)(smem + SM_AHI + base);
            ah[mf][1] = *(const uint32_t*)(smem + SM_AHI + base + 8 * APITCH * 2);
            ah[mf][2] = *(const uint32_t*)(smem + SM_AHI + base + 16);
            ah[mf][3] = *(const uint32_t*)(smem + SM_AHI + base + 8 * APITCH * 2 + 16);
            al[mf][0] = *(const uint32_t*)(smem + SM_ALO + base);
            al[mf][1] = *(const uint32_t*)(smem + SM_ALO + base + 8 * APITCH * 2);
            al[mf][2] = *(const uint32_t*)(smem + SM_ALO + base + 16);
            al[mf][3] = *(const uint32_t*)(smem + SM_ALO + base + 8 * APITCH * 2 + 16);
        }
#pragma unroll
        for (int nf = 0; nf < 4; nf++) {
            uint32_t base = (uint32_t)(warp_n * 32 + nf * 8 + groupID) * (APITCH * 2) + kb;
            bh[nf][0] = *(const uint32_t*)(smem + SM_BHI + base);
            bh[nf][1] = *(const uint32_t*)(smem + SM_BHI + base + 16);
            bl[nf][0] = *(const uint32_t*)(smem + SM_BLO + base);
            bl[nf][1] = *(const uint32_t*)(smem + SM_BLO + base + 16);
        }
#pragma unroll
        for (int mf = 0; mf < 4; mf++)
#pragma unroll
            for (int nf = 0; nf < 4; nf++) {
                mma16816(acc[mf][nf], ah[mf], bh[nf]);
                mma16816(acc[mf][nf], ah[mf], bl[nf]);
                mma16816(acc[mf][nf], al[mf], bh[nf]);
            }
    }

    // ---- epilogue ----
    float cs[4][2] = {}, cq[4][2] = {};
#pragma unroll
    for (int mf = 0; mf < 4; mf++) {
        int r0 = block_row + warp_m * 64 + mf * 16 + groupID;
        int r1 = r0 + 8;
#pragma unroll
        for (int nf = 0; nf < 4; nf++) {
            int c0 = warp_n * 32 + nf * 8 + 2 * tig;
            float b0 = sh_bias[c0], b1 = sh_bias[c0 + 1];
            float t00 = acc[mf][nf][0] + b0, t01 = acc[mf][nf][1] + b1;
            float t10 = acc[mf][nf][2] + b0, t11 = acc[mf][nf][3] + b1;
            if (MODE == 1) {
                t00 = fmaxf(t00, 0.f); t01 = fmaxf(t01, 0.f);
                t10 = fmaxf(t10, 0.f); t11 = fmaxf(t11, 0.f);
            }
            if (r0 < nrows) {
                *reinterpret_cast<float2*>(out + (size_t)r0 * HH + c0) =
                    make_float2(t00, t01);
                if (MODE == 0) {
                    cs[nf][0] += t00; cq[nf][0] = fmaf(t00, t00, cq[nf][0]);
                    cs[nf][1] += t01; cq[nf][1] = fmaf(t01, t01, cq[nf][1]);
                }
            }
            if (r1 < nrows) {
                *reinterpret_cast<float2*>(out + (size_t)r1 * HH + c0) =
                    make_float2(t10, t11);
                if (MODE == 0) {
                    cs[nf][0] += t10; cq[nf][0] = fmaf(t10, t10, cq[nf][0]);
                    cs[nf][1] += t11; cq[nf][1] = fmaf(t11, t11, cq[nf][1]);
                }
            }
        }
    }
    if (MODE == 0) {
#pragma unroll
        for (int nf = 0; nf < 4; nf++)
#pragma unroll
            for (int j = 0; j < 2; j++) {
                float s = cs[nf][j], q = cq[nf][j];
#pragma unroll
                for (int off = 16; off >= 4; off >>= 1) {
                    s += __shfl_down_sync(0xffffffff, s, off);
                    q += __shfl_down_sync(0xffffffff, q, off);
                }
                if (lane < 4) {
                    int col = warp_n * 32 + nf * 8 + 2 * lane + j;
                    atomicAdd(&g_stats[col], s);
                    atomicAdd(&g_stats[128 + col], q);
                }
            }
    }
}

// ---------------- segment-CSR readout ----------------
__global__ void readout_kernel(const float* __restrict__ h,
                               const int* __restrict__ ptr,
                               float* __restrict__ out) {
    int g = blockIdx.x;
    int c = threadIdx.x;
    int s = ptr[g], e = ptr[g + 1];
    float acc = 0.f;
    for (int r = s; r < e; r++) acc += h[r * HH + c];
    out[g * HH + c] = acc;
}

// ---------------- host launch ----------------
extern "C" void kernel_launch(void* const* d_in, const int* in_sizes, int n_in,
                              void* d_out, int out_size) {
    const float* x = (const float*)d_in[0];
    const int* src = (const int*)d_in[1];
    const int* dst = (const int*)d_in[2];
    const int* ptr = (const int*)d_in[3];
    int E = in_sizes[1];
    int N = in_sizes[0] / HH;
    int G = in_sizes[3] - 1;
    float* out = (float*)d_out;

    float *z, *hA, *hB, *stats;
    int *deg, *cursor, *rowstart, *csr;
    uint2 *ahi, *alo;
    unsigned short* wimg;
    cudaGetSymbolAddress((void**)&z, g_z);
    cudaGetSymbolAddress((void**)&hA, g_hA);
    cudaGetSymbolAddress((void**)&hB, g_hB);
    cudaGetSymbolAddress((void**)&stats, g_stats);
    cudaGetSymbolAddress((void**)&deg, g_deg);
    cudaGetSymbolAddress((void**)&cursor, g_cursor);
    cudaGetSymbolAddress((void**)&rowstart, g_rowstart);
    cudaGetSymbolAddress((void**)&csr, g_csr);
    cudaGetSymbolAddress((void**)&ahi, g_ahi);
    cudaGetSymbolAddress((void**)&alo, g_alo);
    cudaGetSymbolAddress((void**)&wimg, g_w);

    cudaFuncSetAttribute(gemm_mma<0>, cudaFuncAttributeMaxDynamicSharedMemorySize, SM_TOTAL);
    cudaFuncSetAttribute(gemm_mma<1>, cudaFuncAttributeMaxDynamicSharedMemorySize, SM_TOTAL);

    int gemm_blocks = (N + 127) / 128;
    int eb = (E + 255) / 256;
    int agg_blocks = (int)(((long long)N * 32 + 255) / 256);
    float inv_n = 1.0f / (float)N;

    // ---- W image pre-conversion: 6 GEMMs x (hi,lo) ----
    for (int li = 0; li < 3; li++) {
        const float* wa = (const float*)d_in[4 + 6 * li + 0];
        const float* wb = (const float*)d_in[4 + 6 * li + 4];
        wconv_kernel<<<64, 256>>>(wa, wimg + (size_t)(4 * li + 0) * WIMG_ELEMS,
                                      wimg + (size_t)(4 * li + 1) * WIMG_ELEMS);
        wconv_kernel<<<64, 256>>>(wb, wimg + (size_t)(4 * li + 2) * WIMG_ELEMS,
                                      wimg + (size_t)(4 * li + 3) * WIMG_ELEMS);
    }

    // ---- CSR build (once, reused by all 3 layers) ----
    cudaMemsetAsync(deg, 0, N * sizeof(int));
    cudaMemsetAsync(cursor, 0, N * sizeof(int));
    count_kernel<<<eb, 256>>>(dst, deg, E);
    scan_kernel<<<1, 1024>>>(deg, rowstart, N);
    fill_kernel<<<eb, 256>>>(src, dst, rowstart, cursor, csr, E);

    auto layer = [&](const float* hin, float* hout, int li) {
        int base = 4 + 6 * li;
        const float* ba = (const float*)d_in[base + 1];
        const float* ga = (const float*)d_in[base + 2];
        const float* be = (const float*)d_in[base + 3];
        const float* bb = (const float*)d_in[base + 5];
        const uint4* wahi = (const uint4*)(wimg + (size_t)(4 * li + 0) * WIMG_ELEMS);
        const uint4* walo = (const uint4*)(wimg + (size_t)(4 * li + 1) * WIMG_ELEMS);
        const uint4* wbhi = (const uint4*)(wimg + (size_t)(4 * li + 2) * WIMG_ELEMS);
        const uint4* wblo = (const uint4*)(wimg + (size_t)(4 * li + 3) * WIMG_ELEMS);

        cudaMemsetAsync(stats, 0, 2 * HH * sizeof(float));
        aggregate_kernel<<<agg_blocks, 256>>>((const float4*)hin, rowstart, csr,
                                              ahi, alo, N);
        gemm_mma<0><<<gemm_blocks, 256, SM_TOTAL>>>(
            nullptr, (const uint4*)ahi, (const uint4*)alo, wahi, walo,
            ba, nullptr, nullptr, 0.f, z, N);
        gemm_mma<1><<<gemm_blocks, 256, SM_TOTAL>>>(
            z, nullptr, nullptr, wbhi, wblo,
            bb, ga, be, inv_n, hout, N);
    };

    layer(x, hA, 0);
    layer(hA, hB, 1);
    layer(hB, hA, 2);

    readout_kernel<<<G, 128>>>(hA, ptr, out);
}